// round 5
// baseline (speedup 1.0000x reference)
#include <cuda_runtime.h>
#include <cuda_bf16.h>

// Sparsemax along last dim, rows of N=2048 fp32. One warp per row.
//
// tau in [M-1, M)  =>  support ⊆ {x > M-1} (~7 of 2048, Gaussian rows).
// R5: do NOT keep the row in registers (that cost 64 regs -> 26% occupancy).
//   pass A: stream the row (__ldcg, L2-resident), maintain per-lane TOP-3
//           via a 5-op sorting-network insert. M = warp-max of c0.
//           Candidates {x > M-1} ⊆ per-lane {c0,c1} unless some lane's
//           c2 > M-1 (then exact fallback re-scans from L2).
//   Newton fixed point on 2 regs/lane; tau1 = (S-1)/C >= M-1, monotone up,
//   so c2 <= thr <= tau can never re-enter the support.
//   pass C: re-read the row from L2 (__ldlu last-use) and emit relu(x-tau)
//           with __stcs streaming stores.
// ~50 regs -> 9 blocks/SM (36 warps) vs R4's 20: more staggered warps to
// keep DRAM busy through each warp's serial phase.

constexpr int ROW_N   = 2048;
constexpr int WARPS_B = 4;
constexpr int THREADS = 32 * WARPS_B;   // 128

__global__ __launch_bounds__(THREADS, 9)
void sparsemax_kernel(const float* __restrict__ in, float* __restrict__ out,
                      int rows) {
    const int lane = threadIdx.x & 31;
    const int row  = blockIdx.x * WARPS_B + (threadIdx.x >> 5);
    if (row >= rows) return;

    const float4* x4 = (const float4*)(in  + (size_t)row * ROW_N);
    float4*       y4 = (float4*)      (out + (size_t)row * ROW_N);

    const float NEG = -3.0e38f;
    float c0 = NEG, c1 = NEG, c2 = NEG;

    // ---- pass A: stream row in 2 chunks of 8 float4, track per-lane top-3 ----
#pragma unroll
    for (int h = 0; h < 2; h++) {
        float4 b[8];
#pragma unroll
        for (int i = 0; i < 8; i++)
            b[i] = __ldcg(&x4[lane + 32 * (8 * h + i)]);
#pragma unroll
        for (int i = 0; i < 8; i++) {
            float e[4] = {b[i].x, b[i].y, b[i].z, b[i].w};
#pragma unroll
            for (int j = 0; j < 4; j++) {
                float x  = e[j];
                float t0 = fminf(c0, x);  c0 = fmaxf(c0, x);
                float t1 = fminf(c1, t0); c1 = fmaxf(c1, t0);
                c2 = fmaxf(c2, t1);
            }
        }
    }

    // ---- row max, threshold ----
    float M = c0;
#pragma unroll
    for (int o = 16; o; o >>= 1)
        M = fmaxf(M, __shfl_xor_sync(0xffffffffu, M, o));
    const float thr = M - 1.0f;

    // lane's 3rd-best above thr => a 4th candidate might exist unseen
    const bool fallback = __any_sync(0xffffffffu, c2 > thr);

    float tau;
    if (!fallback) {
        // ---- fast path: all candidates live in {c0, c1} per lane ----
        float s = 0.f, c = 0.f;
        if (c0 > thr) { s += c0; c += 1.f; }
        if (c1 > thr) { s += c1; c += 1.f; }
#pragma unroll
        for (int o = 16; o; o >>= 1) {
            s += __shfl_xor_sync(0xffffffffu, s, o);
            c += __shfl_xor_sync(0xffffffffu, c, o);
        }
        tau = (s - 1.0f) / c;              // >= thr; monotone up from here
        int kprev = (int)c;

        for (int iter = 0; iter < 40; ++iter) {
            float s2 = 0.f, c2f = 0.f;
            if (c0 > tau) { s2 += c0; c2f += 1.f; }
            if (c1 > tau) { s2 += c1; c2f += 1.f; }
#pragma unroll
            for (int o = 16; o; o >>= 1) {
                s2  += __shfl_xor_sync(0xffffffffu, s2, o);
                c2f += __shfl_xor_sync(0xffffffffu, c2f, o);
            }
            int k2 = (int)c2f;             // max element always survives
            tau = (s2 - 1.0f) / c2f;
            if (k2 == kprev) break;        // support stable -> exact
            kprev = k2;
        }
    } else {
        // ---- generic exact path: re-scan row (L2-hit) per iteration ----
        float t2 = thr;
        int kprev = -1;
        for (int iter = 0; iter < 64; ++iter) {
            float s = 0.f, c = 0.f;
            for (int i = lane; i < ROW_N / 4; i += 32) {
                float4 b = __ldcg(&x4[i]);
                if (b.x > t2) { s += b.x; c += 1.f; }
                if (b.y > t2) { s += b.y; c += 1.f; }
                if (b.z > t2) { s += b.z; c += 1.f; }
                if (b.w > t2) { s += b.w; c += 1.f; }
            }
#pragma unroll
            for (int o = 16; o; o >>= 1) {
                s += __shfl_xor_sync(0xffffffffu, s, o);
                c += __shfl_xor_sync(0xffffffffu, c, o);
            }
            int k = (int)c;
            t2 = (s - 1.0f) / c;
            if (k == kprev) break;
            kprev = k;
        }
        tau = t2;
    }

    // ---- pass C: re-read row (L2 hit, last-use) and write relu(x - tau) ----
#pragma unroll
    for (int h = 0; h < 2; h++) {
        float4 b[8];
#pragma unroll
        for (int i = 0; i < 8; i++)
            b[i] = __ldlu(&x4[lane + 32 * (8 * h + i)]);
#pragma unroll
        for (int i = 0; i < 8; i++) {
            float4 o;
            o.x = fmaxf(b[i].x - tau, 0.f);
            o.y = fmaxf(b[i].y - tau, 0.f);
            o.z = fmaxf(b[i].z - tau, 0.f);
            o.w = fmaxf(b[i].w - tau, 0.f);
            __stcs(&y4[lane + 32 * (8 * h + i)], o);
        }
    }
}

extern "C" void kernel_launch(void* const* d_in, const int* in_sizes, int n_in,
                              void* d_out, int out_size) {
    const float* in = (const float*)d_in[0];
    float* out = (float*)d_out;
    int rows = in_sizes[0] / ROW_N;              // 65536
    int grid = (rows + WARPS_B - 1) / WARPS_B;   // 16384
    sparsemax_kernel<<<grid, THREADS>>>(in, out, rows);
}

// round 6
// speedup vs baseline: 1.0919x; 1.0919x over previous
#include <cuda_runtime.h>
#include <cuda_bf16.h>

// Sparsemax, rows of N=2048 fp32. One 128-thread block (4 warps) per row.
// Row register-resident: 4 float4/lane (16 regs) -> ~38 total regs -> 12
// blocks/SM (vs R4's 64 data regs -> occ 26%).
//
// tau in [M-1, M) => support ⊆ {x > M-1} (~7 elems for Gaussian rows).
//   1. block max M (shfl + 4-slot smem + 1 bar)
//   2. per-lane top-2 (register insert) + exact per-lane count of {x>M-1};
//      publish top-2 (NEG-padded) to a fixed smem[256]; 1 bar
//   3. warp 0 alone: Newton fixed point tau <- (sum_{>tau}-1)/cnt over the
//      256 smem slots (8/lane), shfl reductions, exact stop when support
//      count is stable; 1 bar to broadcast tau
//      (if any lane counted >2 candidates: exact block-wide fallback over
//       the register-resident row — degenerate inputs only)
//   4. output relu(x - tau) from registers.

constexpr int ROW_N   = 2048;
constexpr int THREADS = 128;
constexpr int NWARP   = THREADS / 32;        // 4
constexpr int F4PT    = ROW_N / 4 / THREADS; // 4

__global__ __launch_bounds__(THREADS, 12)
void sparsemax_kernel(const float* __restrict__ in, float* __restrict__ out) {
    __shared__ float pm[NWARP];
    __shared__ float ps[NWARP];
    __shared__ float pc[NWARP];
    __shared__ float cand[2 * THREADS];      // 256 slots, NEG-padded
    __shared__ float stau;
    __shared__ int   sflag;

    const int t    = threadIdx.x;
    const int lane = t & 31;
    const int wid  = t >> 5;
    const size_t row = blockIdx.x;

    const float4* x4 = (const float4*)(in  + row * (size_t)ROW_N);
    float4*       y4 = (float4*)      (out + row * (size_t)ROW_N);

    // ---- load: 4 coalesced LDG.128 per lane, front-batched ----
    float4 a[F4PT];
#pragma unroll
    for (int i = 0; i < F4PT; i++) a[i] = __ldcs(&x4[t + THREADS * i]);

    // ---- block max ----
    float m = fmaxf(fmaxf(a[0].x, a[0].y), fmaxf(a[0].z, a[0].w));
#pragma unroll
    for (int i = 1; i < F4PT; i++)
        m = fmaxf(m, fmaxf(fmaxf(a[i].x, a[i].y), fmaxf(a[i].z, a[i].w)));
#pragma unroll
    for (int o = 16; o; o >>= 1)
        m = fmaxf(m, __shfl_xor_sync(0xffffffffu, m, o));
    if (lane == 0) pm[wid] = m;
    if (t == 0) sflag = 0;
    __syncthreads();                                       // bar 1

    float M = fmaxf(fmaxf(pm[0], pm[1]), fmaxf(pm[2], pm[3]));
    const float thr = M - 1.0f;

    // ---- per-lane top-2 insert (3-op network) + exact candidate count ----
    const float NEG = -3.0e38f;
    float c0 = NEG, c1 = NEG;
    int nc = 0;
#pragma unroll
    for (int i = 0; i < F4PT; i++) {
        float e[4] = {a[i].x, a[i].y, a[i].z, a[i].w};
#pragma unroll
        for (int j = 0; j < 4; j++) {
            float x = e[j];
            nc += (x > thr);                 // independent, no chain
            float t0 = fminf(c0, x);
            c0 = fmaxf(c0, x);
            c1 = fmaxf(c1, t0);
        }
    }
    float q0 = (c0 > thr) ? c0 : NEG;
    float q1 = (c1 > thr) ? c1 : NEG;
    cand[2 * t]     = q0;
    cand[2 * t + 1] = q1;

    float s = (q0 > NEG ? q0 : 0.f) + (q1 > NEG ? q1 : 0.f);
    float c = (float)((q0 > NEG) + (q1 > NEG));
#pragma unroll
    for (int o = 16; o; o >>= 1) {
        s += __shfl_xor_sync(0xffffffffu, s, o);
        c += __shfl_xor_sync(0xffffffffu, c, o);
    }
    if (lane == 0) { ps[wid] = s; pc[wid] = c; }
    if (__ballot_sync(0xffffffffu, nc > 2)) sflag = 1;     // benign race
    __syncthreads();                                       // bar 2

    float tau;
    if (sflag == 0) {
        // ---- fast path: warp 0 Newton over the 256 smem candidate slots ----
        if (wid == 0) {
            float S = ps[0] + ps[1] + ps[2] + ps[3];
            float C = pc[0] + pc[1] + pc[2] + pc[3];
            float tl = (S - 1.0f) / C;       // >= thr, monotone up from here
            int kprev = (int)C;

            for (int iter = 0; iter < 40; ++iter) {
                float s2 = 0.f, c2 = 0.f;
#pragma unroll
                for (int j = 0; j < 8; j++) {
                    float w = cand[lane + 32 * j];
                    if (w > tl) { s2 += w; c2 += 1.f; }
                }
#pragma unroll
                for (int o = 16; o; o >>= 1) {
                    s2 += __shfl_xor_sync(0xffffffffu, s2, o);
                    c2 += __shfl_xor_sync(0xffffffffu, c2, o);
                }
                int k2 = (int)c2;            // max element always survives
                tl = (s2 - 1.0f) / c2;
                if (k2 == kprev) break;      // support stable -> exact
                kprev = k2;
            }
            if (lane == 0) stau = tl;
        }
        __syncthreads();                                   // bar 3
        tau = stau;
    } else {
        // ---- exact fallback (degenerate rows): block-wide Newton over regs ----
        tau = thr;
        int kprev = -1;
        for (int iter = 0; iter < 64; ++iter) {
            float s2 = 0.f, c2 = 0.f;
#pragma unroll
            for (int i = 0; i < F4PT; i++) {
                if (a[i].x > tau) { s2 += a[i].x; c2 += 1.f; }
                if (a[i].y > tau) { s2 += a[i].y; c2 += 1.f; }
                if (a[i].z > tau) { s2 += a[i].z; c2 += 1.f; }
                if (a[i].w > tau) { s2 += a[i].w; c2 += 1.f; }
            }
#pragma unroll
            for (int o = 16; o; o >>= 1) {
                s2 += __shfl_xor_sync(0xffffffffu, s2, o);
                c2 += __shfl_xor_sync(0xffffffffu, c2, o);
            }
            if (lane == 0) { ps[wid] = s2; pc[wid] = c2; }
            __syncthreads();
            float S2 = ps[0] + ps[1] + ps[2] + ps[3];
            float C2 = pc[0] + pc[1] + pc[2] + pc[3];
            int k2 = (int)C2;
            tau = (S2 - 1.0f) / C2;
            __syncthreads();                 // ps/pc reusable next iter
            if (k2 == kprev) break;
            kprev = k2;
        }
    }

    // ---- output: relu(x - tau) from registers ----
#pragma unroll
    for (int i = 0; i < F4PT; i++) {
        float4 o;
        o.x = fmaxf(a[i].x - tau, 0.f);
        o.y = fmaxf(a[i].y - tau, 0.f);
        o.z = fmaxf(a[i].z - tau, 0.f);
        o.w = fmaxf(a[i].w - tau, 0.f);
        __stcs(&y4[t + THREADS * i], o);
    }
}

extern "C" void kernel_launch(void* const* d_in, const int* in_sizes, int n_in,
                              void* d_out, int out_size) {
    const float* in = (const float*)d_in[0];
    float* out = (float*)d_out;
    int rows = in_sizes[0] / ROW_N;          // 65536
    sparsemax_kernel<<<rows, THREADS>>>(in, out);
}

// round 7
// speedup vs baseline: 1.0982x; 1.0057x over previous
#include <cuda_runtime.h>
#include <cuda_bf16.h>

// Sparsemax, rows of N=2048 fp32. One 128-thread block (4 warps) per row,
// row register-resident (4 float4/lane).
//
// tau in [M-1, M) => support ⊆ {x > M-1} (~7 elems for Gaussian rows).
//   1. block max M (shfl + 4-slot smem + 1 bar)
//   2. per-lane top-2 above M-1 published to fixed smem[256] (NEG-padded),
//      exact per-lane candidate count nc; 1 bar
//   3. ALL warps redundantly run the Newton fixed point
//         tau <- (sum_{x>tau} - 1)/count
//      over the 256 candidate slots starting at tau = M-1 (first iteration
//      reproduces (S-1)/C, so no pre-reduction needed). Stops exactly when
//      the support count is stable. No third barrier, no tau broadcast.
//      If any lane saw nc>2 (degenerate rows), exact block-wide fallback
//      over the register-resident row.
//   4. output relu(x - tau) from registers.
//
// R6 established DRAM=84.5% at both occ 26% and 72% -> ~6.7 TB/s is the
// practical mixed r/w HBM ceiling; this round only trims serial-phase ops.

constexpr int ROW_N   = 2048;
constexpr int THREADS = 128;
constexpr int NWARP   = THREADS / 32;        // 4
constexpr int F4PT    = ROW_N / 4 / THREADS; // 4

__global__ __launch_bounds__(THREADS, 12)
void sparsemax_kernel(const float* __restrict__ in, float* __restrict__ out) {
    __shared__ float pm[NWARP];
    __shared__ float ps[NWARP];
    __shared__ float pc[NWARP];
    __shared__ float cand[2 * THREADS];      // 256 slots, NEG-padded
    __shared__ int   sflag;

    const int t    = threadIdx.x;
    const int lane = t & 31;
    const int wid  = t >> 5;
    const size_t row = blockIdx.x;

    const float4* x4 = (const float4*)(in  + row * (size_t)ROW_N);
    float4*       y4 = (float4*)      (out + row * (size_t)ROW_N);

    // ---- load: 4 coalesced LDG.128 per lane, front-batched ----
    float4 a[F4PT];
#pragma unroll
    for (int i = 0; i < F4PT; i++) a[i] = __ldcs(&x4[t + THREADS * i]);

    // ---- block max ----
    float m = fmaxf(fmaxf(a[0].x, a[0].y), fmaxf(a[0].z, a[0].w));
#pragma unroll
    for (int i = 1; i < F4PT; i++)
        m = fmaxf(m, fmaxf(fmaxf(a[i].x, a[i].y), fmaxf(a[i].z, a[i].w)));
#pragma unroll
    for (int o = 16; o; o >>= 1)
        m = fmaxf(m, __shfl_xor_sync(0xffffffffu, m, o));
    if (lane == 0) pm[wid] = m;
    if (t == 0) sflag = 0;
    __syncthreads();                                       // bar 1

    float M = fmaxf(fmaxf(pm[0], pm[1]), fmaxf(pm[2], pm[3]));
    const float thr = M - 1.0f;

    // ---- per-lane top-2 insert + exact candidate count (no reductions) ----
    const float NEG = -3.0e38f;
    float c0 = NEG, c1 = NEG;
    int nc = 0;
#pragma unroll
    for (int i = 0; i < F4PT; i++) {
        float e[4] = {a[i].x, a[i].y, a[i].z, a[i].w};
#pragma unroll
        for (int j = 0; j < 4; j++) {
            float x = e[j];
            nc += (x > thr);                 // independent of the chain below
            float t0 = fminf(c0, x);
            c0 = fmaxf(c0, x);
            c1 = fmaxf(c1, t0);
        }
    }
    cand[2 * t]     = (c0 > thr) ? c0 : NEG;
    cand[2 * t + 1] = (c1 > thr) ? c1 : NEG;
    if (__ballot_sync(0xffffffffu, nc > 2)) sflag = 1;     // benign race
    __syncthreads();                                       // bar 2

    float tau;
    if (sflag == 0) {
        // ---- fast path: every warp runs the same tiny Newton (no bar) ----
        tau = thr;                           // iter 1 yields (S-1)/C exactly
        int kprev = -1;
        for (int iter = 0; iter < 40; ++iter) {
            float s2 = 0.f, c2 = 0.f;
#pragma unroll
            for (int j = 0; j < 8; j++) {
                float w = cand[lane + 32 * j];
                if (w > tau) { s2 += w; c2 += 1.f; }
            }
#pragma unroll
            for (int o = 16; o; o >>= 1) {
                s2 += __shfl_xor_sync(0xffffffffu, s2, o);
                c2 += __shfl_xor_sync(0xffffffffu, c2, o);
            }
            int k2 = (int)c2;                // max element always survives
            tau = (s2 - 1.0f) / c2;
            if (k2 == kprev) break;          // support stable -> exact
            kprev = k2;
        }
    } else {
        // ---- exact fallback (degenerate rows): block-wide Newton over regs ----
        tau = thr;
        int kprev = -1;
        for (int iter = 0; iter < 64; ++iter) {
            float s2 = 0.f, c2 = 0.f;
#pragma unroll
            for (int i = 0; i < F4PT; i++) {
                if (a[i].x > tau) { s2 += a[i].x; c2 += 1.f; }
                if (a[i].y > tau) { s2 += a[i].y; c2 += 1.f; }
                if (a[i].z > tau) { s2 += a[i].z; c2 += 1.f; }
                if (a[i].w > tau) { s2 += a[i].w; c2 += 1.f; }
            }
#pragma unroll
            for (int o = 16; o; o >>= 1) {
                s2 += __shfl_xor_sync(0xffffffffu, s2, o);
                c2 += __shfl_xor_sync(0xffffffffu, c2, o);
            }
            if (lane == 0) { ps[wid] = s2; pc[wid] = c2; }
            __syncthreads();
            float S2 = ps[0] + ps[1] + ps[2] + ps[3];
            float C2 = pc[0] + pc[1] + pc[2] + pc[3];
            int k2 = (int)C2;
            tau = (S2 - 1.0f) / C2;
            __syncthreads();                 // ps/pc reusable next iter
            if (k2 == kprev) break;
            kprev = k2;
        }
    }

    // ---- output: relu(x - tau) from registers ----
#pragma unroll
    for (int i = 0; i < F4PT; i++) {
        float4 o;
        o.x = fmaxf(a[i].x - tau, 0.f);
        o.y = fmaxf(a[i].y - tau, 0.f);
        o.z = fmaxf(a[i].z - tau, 0.f);
        o.w = fmaxf(a[i].w - tau, 0.f);
        __stcs(&y4[t + THREADS * i], o);
    }
}

extern "C" void kernel_launch(void* const* d_in, const int* in_sizes, int n_in,
                              void* d_out, int out_size) {
    const float* in = (const float*)d_in[0];
    float* out = (float*)d_out;
    int rows = in_sizes[0] / ROW_N;          // 65536
    sparsemax_kernel<<<rows, THREADS>>>(in, out);
}

// round 8
// speedup vs baseline: 1.1006x; 1.0023x over previous
#include <cuda_runtime.h>
#include <cuda_bf16.h>

// Sparsemax, rows of N=2048 fp32. One 128-thread block handles TWO rows
// (rows 2b, 2b+1), each row 4 float4/lane register-resident.
//
// tau in [M-1, M) => support ⊆ {x > M-1} (~7 elems for Gaussian rows).
// Both rows are loaded up front (8 front-batched LDG.128 -> MLP 8); both
// max-reductions and both candidate builds share ONE barrier each, so the
// barrier cost per row halves vs R7. Newton fixed point
//    tau <- (sum_{x>tau} - 1)/count
// over a 256-slot smem candidate list (per row), run redundantly by all
// warps (no broadcast barrier); exact stop when support count stable.
// Degenerate rows (any lane >2 candidates above thr) take an exact
// block-wide fallback over the register-resident row.

constexpr int ROW_N   = 2048;
constexpr int THREADS = 128;
constexpr int NWARP   = THREADS / 32;        // 4
constexpr int F4PT    = ROW_N / 4 / THREADS; // 4

__device__ __forceinline__ float block_newton_fast(const float* cand,
                                                   float thr, int lane) {
    float tau = thr;                       // iter 1 reproduces (S-1)/C
    int kprev = -1;
    for (int iter = 0; iter < 40; ++iter) {
        float s2 = 0.f, c2 = 0.f;
#pragma unroll
        for (int j = 0; j < 8; j++) {
            float w = cand[lane + 32 * j];
            if (w > tau) { s2 += w; c2 += 1.f; }
        }
#pragma unroll
        for (int o = 16; o; o >>= 1) {
            s2 += __shfl_xor_sync(0xffffffffu, s2, o);
            c2 += __shfl_xor_sync(0xffffffffu, c2, o);
        }
        int k2 = (int)c2;                  // max element always survives
        tau = (s2 - 1.0f) / c2;
        if (k2 == kprev) break;            // support stable -> exact
        kprev = k2;
    }
    return tau;
}

__device__ __forceinline__ float block_newton_fallback(const float4* a,
                                                       float thr, int lane,
                                                       int wid, float* ps,
                                                       float* pc) {
    float tau = thr;
    int kprev = -1;
    for (int iter = 0; iter < 64; ++iter) {
        float s2 = 0.f, c2 = 0.f;
#pragma unroll
        for (int i = 0; i < F4PT; i++) {
            if (a[i].x > tau) { s2 += a[i].x; c2 += 1.f; }
            if (a[i].y > tau) { s2 += a[i].y; c2 += 1.f; }
            if (a[i].z > tau) { s2 += a[i].z; c2 += 1.f; }
            if (a[i].w > tau) { s2 += a[i].w; c2 += 1.f; }
        }
#pragma unroll
        for (int o = 16; o; o >>= 1) {
            s2 += __shfl_xor_sync(0xffffffffu, s2, o);
            c2 += __shfl_xor_sync(0xffffffffu, c2, o);
        }
        if (lane == 0) { ps[wid] = s2; pc[wid] = c2; }
        __syncthreads();
        float S2 = ps[0] + ps[1] + ps[2] + ps[3];
        float C2 = pc[0] + pc[1] + pc[2] + pc[3];
        int k2 = (int)C2;
        tau = (S2 - 1.0f) / C2;
        __syncthreads();
        if (k2 == kprev) break;
        kprev = k2;
    }
    return tau;
}

__global__ __launch_bounds__(THREADS, 9)
void sparsemax_kernel(const float* __restrict__ in, float* __restrict__ out) {
    __shared__ float pm0[NWARP], pm1[NWARP];
    __shared__ float ps[NWARP], pc[NWARP];
    __shared__ float cand0[2 * THREADS];     // NEG-padded
    __shared__ float cand1[2 * THREADS];
    __shared__ int   sflag0, sflag1;

    const int t    = threadIdx.x;
    const int lane = t & 31;
    const int wid  = t >> 5;
    const size_t r0 = (size_t)blockIdx.x * 2;

    const float4* x0 = (const float4*)(in  + r0 * ROW_N);
    const float4* x1 = (const float4*)(in  + (r0 + 1) * ROW_N);
    float4*       y0 = (float4*)      (out + r0 * ROW_N);
    float4*       y1 = (float4*)      (out + (r0 + 1) * ROW_N);

    // ---- load both rows: 8 coalesced LDG.128 per lane, front-batched ----
    float4 a[F4PT], b[F4PT];
#pragma unroll
    for (int i = 0; i < F4PT; i++) a[i] = __ldcs(&x0[t + THREADS * i]);
#pragma unroll
    for (int i = 0; i < F4PT; i++) b[i] = __ldcs(&x1[t + THREADS * i]);

    // ---- both row maxes (interleaved shfl reductions) ----
    float m0 = fmaxf(fmaxf(a[0].x, a[0].y), fmaxf(a[0].z, a[0].w));
    float m1 = fmaxf(fmaxf(b[0].x, b[0].y), fmaxf(b[0].z, b[0].w));
#pragma unroll
    for (int i = 1; i < F4PT; i++) {
        m0 = fmaxf(m0, fmaxf(fmaxf(a[i].x, a[i].y), fmaxf(a[i].z, a[i].w)));
        m1 = fmaxf(m1, fmaxf(fmaxf(b[i].x, b[i].y), fmaxf(b[i].z, b[i].w)));
    }
#pragma unroll
    for (int o = 16; o; o >>= 1) {
        m0 = fmaxf(m0, __shfl_xor_sync(0xffffffffu, m0, o));
        m1 = fmaxf(m1, __shfl_xor_sync(0xffffffffu, m1, o));
    }
    if (lane == 0) { pm0[wid] = m0; pm1[wid] = m1; }
    if (t == 0) { sflag0 = 0; sflag1 = 0; }
    __syncthreads();                                       // bar 1 (both rows)

    const float thr0 = fmaxf(fmaxf(pm0[0], pm0[1]), fmaxf(pm0[2], pm0[3])) - 1.0f;
    const float thr1 = fmaxf(fmaxf(pm1[0], pm1[1]), fmaxf(pm1[2], pm1[3])) - 1.0f;

    // ---- per-lane top-2 + exact count, both rows ----
    const float NEG = -3.0e38f;
    float a0 = NEG, a1 = NEG, b0 = NEG, b1 = NEG;
    int nca = 0, ncb = 0;
#pragma unroll
    for (int i = 0; i < F4PT; i++) {
        float ea[4] = {a[i].x, a[i].y, a[i].z, a[i].w};
        float eb[4] = {b[i].x, b[i].y, b[i].z, b[i].w};
#pragma unroll
        for (int j = 0; j < 4; j++) {
            float xa = ea[j], xb = eb[j];
            nca += (xa > thr0);
            ncb += (xb > thr1);
            float ta = fminf(a0, xa); a0 = fmaxf(a0, xa); a1 = fmaxf(a1, ta);
            float tb = fminf(b0, xb); b0 = fmaxf(b0, xb); b1 = fmaxf(b1, tb);
        }
    }
    cand0[2 * t]     = (a0 > thr0) ? a0 : NEG;
    cand0[2 * t + 1] = (a1 > thr0) ? a1 : NEG;
    cand1[2 * t]     = (b0 > thr1) ? b0 : NEG;
    cand1[2 * t + 1] = (b1 > thr1) ? b1 : NEG;
    if (__ballot_sync(0xffffffffu, nca > 2)) sflag0 = 1;   // benign races
    if (__ballot_sync(0xffffffffu, ncb > 2)) sflag1 = 1;
    __syncthreads();                                       // bar 2 (both rows)

    // ---- row 0: tau + store ----
    float tau0 = (sflag0 == 0)
        ? block_newton_fast(cand0, thr0, lane)
        : block_newton_fallback(a, thr0, lane, wid, ps, pc);
#pragma unroll
    for (int i = 0; i < F4PT; i++) {
        float4 o;
        o.x = fmaxf(a[i].x - tau0, 0.f);
        o.y = fmaxf(a[i].y - tau0, 0.f);
        o.z = fmaxf(a[i].z - tau0, 0.f);
        o.w = fmaxf(a[i].w - tau0, 0.f);
        __stcs(&y0[t + THREADS * i], o);
    }

    // ---- row 1: tau + store ----
    float tau1 = (sflag1 == 0)
        ? block_newton_fast(cand1, thr1, lane)
        : block_newton_fallback(b, thr1, lane, wid, ps, pc);
#pragma unroll
    for (int i = 0; i < F4PT; i++) {
        float4 o;
        o.x = fmaxf(b[i].x - tau1, 0.f);
        o.y = fmaxf(b[i].y - tau1, 0.f);
        o.z = fmaxf(b[i].z - tau1, 0.f);
        o.w = fmaxf(b[i].w - tau1, 0.f);
        __stcs(&y1[t + THREADS * i], o);
    }
}

extern "C" void kernel_launch(void* const* d_in, const int* in_sizes, int n_in,
                              void* d_out, int out_size) {
    const float* in = (const float*)d_in[0];
    float* out = (float*)d_out;
    int rows = in_sizes[0] / ROW_N;          // 65536 (even)
    sparsemax_kernel<<<rows / 2, THREADS>>>(in, out);
}

// round 9
// speedup vs baseline: 1.1038x; 1.0029x over previous
#include <cuda_runtime.h>
#include <cuda_bf16.h>

// Sparsemax, rows of N=2048 fp32. One 128-thread block (4 warps) per row,
// row register-resident (4 float4/lane). FINAL configuration: R7 shape
// (best measured: ncu 151.9us, DRAM 84.6%) with micro-trims only.
//
// tau in [M-1, M) => support ⊆ {x > M-1} (~7 elems for Gaussian rows).
//   1. block max M (shfl + 4-slot smem + 1 bar)
//   2. per-lane top-2 above M-1 published to fixed smem[256] (NEG-padded,
//      float2 per thread), exact per-lane candidate count; 1 bar
//   3. all warps redundantly run the Newton fixed point
//         tau <- (sum_{x>tau} - 1)/count
//      starting at tau = M-1 (first iter reproduces (S-1)/C); candidates
//      read as 4x LDS.64 per lane. Exact stop when support count stable.
//      Degenerate rows (any lane >2 candidates): exact block-wide fallback
//      over the register-resident row.
//   4. output relu(x - tau) from registers, streaming stores.
//
// Evidence across R4-R8: DRAM pins at 6.5-6.7 TB/s (81-85%) regardless of
// occupancy (26-72%) or block shape -> this is the practical mixed r/w HBM
// ceiling; 537MB in + 537MB out is irreducible, so ~152us kernel-internal
// is the floor. This round only trims issue-side ops.

constexpr int ROW_N   = 2048;
constexpr int THREADS = 128;
constexpr int NWARP   = THREADS / 32;        // 4
constexpr int F4PT    = ROW_N / 4 / THREADS; // 4

__global__ __launch_bounds__(THREADS, 12)
void sparsemax_kernel(const float* __restrict__ in, float* __restrict__ out) {
    __shared__ float  pm[NWARP];
    __shared__ float  ps[NWARP];
    __shared__ float  pc[NWARP];
    __shared__ float2 cand[THREADS];         // 256 slots, NEG-padded
    __shared__ int    sflag;

    const int t    = threadIdx.x;
    const int lane = t & 31;
    const int wid  = t >> 5;
    const size_t row = blockIdx.x;

    const float4* x4 = (const float4*)(in  + row * (size_t)ROW_N);
    float4*       y4 = (float4*)      (out + row * (size_t)ROW_N);

    // ---- load: 4 coalesced LDG.128 per lane, front-batched ----
    float4 a[F4PT];
#pragma unroll
    for (int i = 0; i < F4PT; i++) a[i] = __ldcs(&x4[t + THREADS * i]);

    // ---- block max ----
    float m = fmaxf(fmaxf(a[0].x, a[0].y), fmaxf(a[0].z, a[0].w));
#pragma unroll
    for (int i = 1; i < F4PT; i++)
        m = fmaxf(m, fmaxf(fmaxf(a[i].x, a[i].y), fmaxf(a[i].z, a[i].w)));
#pragma unroll
    for (int o = 16; o; o >>= 1)
        m = fmaxf(m, __shfl_xor_sync(0xffffffffu, m, o));
    if (lane == 0) pm[wid] = m;
    if (t == 0) sflag = 0;
    __syncthreads();                                       // bar 1

    float M = fmaxf(fmaxf(pm[0], pm[1]), fmaxf(pm[2], pm[3]));
    const float thr = M - 1.0f;

    // ---- per-lane top-2 insert + exact candidate count ----
    const float NEG = -3.0e38f;
    float c0 = NEG, c1 = NEG;
    int nc = 0;
#pragma unroll
    for (int i = 0; i < F4PT; i++) {
        float e[4] = {a[i].x, a[i].y, a[i].z, a[i].w};
#pragma unroll
        for (int j = 0; j < 4; j++) {
            float x = e[j];
            nc += (x > thr);                 // independent of the chain below
            float t0 = fminf(c0, x);
            c0 = fmaxf(c0, x);
            c1 = fmaxf(c1, t0);
        }
    }
    float2 q;
    q.x = (c0 > thr) ? c0 : NEG;
    q.y = (c1 > thr) ? c1 : NEG;
    cand[t] = q;                             // one STS.64
    if (__ballot_sync(0xffffffffu, nc > 2)) sflag = 1;     // benign race
    __syncthreads();                                       // bar 2

    float tau;
    if (sflag == 0) {
        // ---- fast path: every warp runs the same tiny Newton (no bar) ----
        tau = thr;                           // iter 1 yields (S-1)/C exactly
        int kprev = -1;
        for (int iter = 0; iter < 40; ++iter) {
            float s2 = 0.f, c2 = 0.f;
#pragma unroll
            for (int j = 0; j < 4; j++) {    // 4x LDS.64 per lane
                float2 w = cand[lane + 32 * j];
                if (w.x > tau) { s2 += w.x; c2 += 1.f; }
                if (w.y > tau) { s2 += w.y; c2 += 1.f; }
            }
#pragma unroll
            for (int o = 16; o; o >>= 1) {
                s2 += __shfl_xor_sync(0xffffffffu, s2, o);
                c2 += __shfl_xor_sync(0xffffffffu, c2, o);
            }
            int k2 = (int)c2;                // max element always survives
            tau = (s2 - 1.0f) / c2;
            if (k2 == kprev) break;          // support stable -> exact
            kprev = k2;
        }
    } else {
        // ---- exact fallback (degenerate rows): block-wide Newton over regs ----
        tau = thr;
        int kprev = -1;
        for (int iter = 0; iter < 64; ++iter) {
            float s2 = 0.f, c2 = 0.f;
#pragma unroll
            for (int i = 0; i < F4PT; i++) {
                if (a[i].x > tau) { s2 += a[i].x; c2 += 1.f; }
                if (a[i].y > tau) { s2 += a[i].y; c2 += 1.f; }
                if (a[i].z > tau) { s2 += a[i].z; c2 += 1.f; }
                if (a[i].w > tau) { s2 += a[i].w; c2 += 1.f; }
            }
#pragma unroll
            for (int o = 16; o; o >>= 1) {
                s2 += __shfl_xor_sync(0xffffffffu, s2, o);
                c2 += __shfl_xor_sync(0xffffffffu, c2, o);
            }
            if (lane == 0) { ps[wid] = s2; pc[wid] = c2; }
            __syncthreads();
            float S2 = ps[0] + ps[1] + ps[2] + ps[3];
            float C2 = pc[0] + pc[1] + pc[2] + pc[3];
            int k2 = (int)C2;
            tau = (S2 - 1.0f) / C2;
            __syncthreads();                 // ps/pc reusable next iter
            if (k2 == kprev) break;
            kprev = k2;
        }
    }

    // ---- output: relu(x - tau) from registers ----
#pragma unroll
    for (int i = 0; i < F4PT; i++) {
        float4 o;
        o.x = fmaxf(a[i].x - tau, 0.f);
        o.y = fmaxf(a[i].y - tau, 0.f);
        o.z = fmaxf(a[i].z - tau, 0.f);
        o.w = fmaxf(a[i].w - tau, 0.f);
        __stcs(&y4[t + THREADS * i], o);
    }
}

extern "C" void kernel_launch(void* const* d_in, const int* in_sizes, int n_in,
                              void* d_out, int out_size) {
    const float* in = (const float*)d_in[0];
    float* out = (float*)d_out;
    int rows = in_sizes[0] / ROW_N;          // 65536
    sparsemax_kernel<<<rows, THREADS>>>(in, out);
}